// round 9
// baseline (speedup 1.0000x reference)
#include <cuda_runtime.h>
#include <math.h>

#define NPTS 4096
#define NB   8
#define KNN  10
#define TPB  256
#define LOSS_BLOCKS 128        // 128 * 256 = 32768 = NB * NPTS
#define SORT_TPB 256
#define PPT (NPTS / SORT_TPB)  // 16 points per sort thread
#define NBUK 256
#define FULLMASK 0xFFFFFFFFu

// scratch: normals in ORIGINAL point order
__device__ float g_nrm[2][3][NB * NPTS];
// canonical x-sorted clouds (x, y, z, |c|^2) + original indices + bucket width
__device__ float4         g_sorted[2][NB][NPTS];
__device__ unsigned short g_sidx[2][NB][NPTS];
__device__ float          g_binw[2][NB];

// monotone float -> ordered uint transform (preserves <), handles negatives
__device__ __forceinline__ unsigned fkey(float f) {
    unsigned b = __float_as_uint(f);
    unsigned m = (unsigned)((int)b >> 31) | 0x80000000u;
    return b ^ m;
}
// inverse for positive-distance keys (MSB set)
__device__ __forceinline__ float ikey_pos(unsigned k) {
    return __uint_as_float(k ^ 0x80000000u);
}
// branch-free sorted-insert ripple of packed key into ascending a[0..9]
__device__ __forceinline__ void ripple(unsigned (&a)[KNN], unsigned k) {
#pragma unroll
    for (int r = 0; r < KNN; ++r) {
        unsigned lo = min(a[r], k);
        k = max(a[r], k);
        a[r] = lo;
    }
}

// ---------------------------------------------------------------------------
// counting sort of each (cloud, batch) by x into g_sorted / g_sidx
// ---------------------------------------------------------------------------
__global__ void sort_kernel(const float* __restrict__ pred,
                            const float* __restrict__ gt) {
    const int b     = blockIdx.x;
    const int cloud = blockIdx.y;
    const float* __restrict__ base =
        ((cloud == 0) ? pred : gt) + (size_t)b * 3 * NPTS;
    const int tid  = threadIdx.x;
    const int lane = tid & 31, w = tid >> 5;

    float4 pt[PPT];
    int    bk[PPT];
    float xmn = 3.4e38f, xmx = -3.4e38f;
#pragma unroll
    for (int i = 0; i < PPT; ++i) {
        int idx = tid + i * SORT_TPB;
        float x = base[idx];
        float y = base[NPTS + idx];
        float z = base[2 * NPTS + idx];
        pt[i] = make_float4(x, y, z, fmaf(x, x, fmaf(y, y, z * z)));
        xmn = fminf(xmn, x); xmx = fmaxf(xmx, x);
    }
#pragma unroll
    for (int o = 16; o > 0; o >>= 1) {
        xmn = fminf(xmn, __shfl_xor_sync(FULLMASK, xmn, o));
        xmx = fmaxf(xmx, __shfl_xor_sync(FULLMASK, xmx, o));
    }
    __shared__ float smn[8], smx[8];
    __shared__ float sxmin, sscale;
    __shared__ unsigned cnt[NBUK];
    __shared__ unsigned wtot[8];
    if (lane == 0) { smn[w] = xmn; smx[w] = xmx; }
    cnt[tid] = 0;
    __syncthreads();
    if (tid == 0) {
        float mn = smn[0], mx = smx[0];
#pragma unroll
        for (int i = 1; i < 8; ++i) { mn = fminf(mn, smn[i]); mx = fmaxf(mx, smx[i]); }
        float range = fmaxf(mx - mn, 1e-20f);
        sxmin  = mn;
        sscale = 256.0f / range;
        // conservative bucket width (covers rounding)
        g_binw[cloud][b] = range * (1.0f / 256.0f) * 1.001f + 1e-7f;
    }
    __syncthreads();
    const float xmin = sxmin, scale = sscale;
#pragma unroll
    for (int i = 0; i < PPT; ++i) {
        int k = (int)((pt[i].x - xmin) * scale);
        k = min(max(k, 0), NBUK - 1);
        bk[i] = k;
        atomicAdd(&cnt[k], 1);
    }
    __syncthreads();
    // exclusive scan of 256 bucket counts
    unsigned v = cnt[tid];
    unsigned incl = v;
#pragma unroll
    for (int o = 1; o < 32; o <<= 1) {
        unsigned t = __shfl_up_sync(FULLMASK, incl, o);
        if (lane >= o) incl += t;
    }
    if (lane == 31) wtot[w] = incl;
    __syncthreads();
    if (tid == 0) {
        unsigned run = 0;
#pragma unroll
        for (int i = 0; i < 8; ++i) { unsigned t = wtot[i]; wtot[i] = run; run += t; }
    }
    __syncthreads();
    unsigned excl = incl - v + wtot[w];
    __syncthreads();
    cnt[tid] = excl;
    __syncthreads();
#pragma unroll
    for (int i = 0; i < PPT; ++i) {
        unsigned slot = atomicAdd(&cnt[bk[i]], 1);
        g_sorted[cloud][b][slot] = pt[i];
        g_sidx[cloud][b][slot]   = (unsigned short)(tid + i * SORT_TPB);
    }
}

// ---------------------------------------------------------------------------
// KNN (sliding window over x-sorted cloud) + covariance + smallest eigvec
// ---------------------------------------------------------------------------
__global__ void __launch_bounds__(TPB, 2)
normals_kernel(float* __restrict__ out) {
    extern __shared__ float4 ss[];   // 4096 sorted points = 64 KB

    if (blockIdx.x == 0 && blockIdx.y == 0 && blockIdx.z == 0 && threadIdx.x == 0)
        out[0] = 0.0f;

    const int cloud = blockIdx.z;
    const int b     = blockIdx.y;

    for (int t = threadIdx.x; t < NPTS; t += TPB)
        ss[t] = g_sorted[cloud][b][t];
    __syncthreads();

    const int p = blockIdx.x * TPB + threadIdx.x;   // SORTED query position
    const float4 q = ss[p];
    const float ax = -2.0f * q.x, ay = -2.0f * q.y, az = -2.0f * q.z;
    const float qw = q.w;
    const float W  = g_binw[cloud][b];

    unsigned a[KNN];
#pragma unroll
    for (int r = 0; r < KNN; ++r) a[r] = 0xFF7FF000u;  // fkey(FLT_MAX) & ~0xFFF
    float thr = 3.4e38f;

    const int wbase = p & ~31;      // warp-uniform window anchor

#define DIST(c) fmaf(ax, (c).x, fmaf(ay, (c).y, fmaf(az, (c).z, (c).w + qw)))
#define INS(d, idx)                                                     \
    if ((d) < thr) {                                                    \
        ripple(a, (fkey(d) & 0xFFFFF000u) | (unsigned)(idx));           \
        thr = ikey_pos(a[KNN - 1] | 0xFFFu);                            \
    }

    // ---- initial window: the warp's own 32 sorted positions ----
#pragma unroll
    for (int k0 = 0; k0 < 32; k0 += 4) {
        float4 c0 = ss[wbase + k0 + 0];
        float4 c1 = ss[wbase + k0 + 1];
        float4 c2 = ss[wbase + k0 + 2];
        float4 c3 = ss[wbase + k0 + 3];
        float d0 = DIST(c0), d1 = DIST(c1), d2 = DIST(c2), d3 = DIST(c3);
        INS(d0, wbase + k0 + 0)
        INS(d1, wbase + k0 + 1)
        INS(d2, wbase + k0 + 2)
        INS(d3, wbase + k0 + 3)
    }

    // ---- symmetric expansion, 4 candidates per side per step ----
    int jr = wbase + 32, jl = wbase - 1;
    bool myr = false, myl = false;
    bool rmore = (jr < NPTS), lmore = (jl >= 0);

    while (rmore || lmore) {
        if (rmore) {
            int i1 = min(jr + 1, NPTS - 1);
            int i2 = min(jr + 2, NPTS - 1);
            int i3 = min(jr + 3, NPTS - 1);
            float4 c0 = ss[jr], c1 = ss[i1], c2 = ss[i2], c3 = ss[i3];
            float d0 = DIST(c0), d1 = DIST(c1), d2 = DIST(c2), d3 = DIST(c3);
            INS(d0, jr)
            if (jr + 1 < NPTS) { INS(d1, jr + 1) }
            if (jr + 2 < NPTS) { INS(d2, jr + 2) }
            if (jr + 3 < NPTS) { INS(d3, jr + 3) }
            // all indices > jr+3 have x >= c3.x - W (bucket-order bound)
            float dxr = c3.x - q.x - W;
            if (dxr > 0.0f && dxr * dxr >= thr) myr = true;
            jr += 4;
            rmore = (jr < NPTS) && (__ballot_sync(FULLMASK, !myr) != 0u);
        }
        if (lmore) {
            int i1 = max(jl - 1, 0);
            int i2 = max(jl - 2, 0);
            int i3 = max(jl - 3, 0);
            float4 c0 = ss[jl], c1 = ss[i1], c2 = ss[i2], c3 = ss[i3];
            float d0 = DIST(c0), d1 = DIST(c1), d2 = DIST(c2), d3 = DIST(c3);
            INS(d0, jl)
            if (jl - 1 >= 0) { INS(d1, jl - 1) }
            if (jl - 2 >= 0) { INS(d2, jl - 2) }
            if (jl - 3 >= 0) { INS(d3, jl - 3) }
            // all indices < jl-3 have x <= c3.x + W
            float dxl = q.x - c3.x - W;
            if (dxl > 0.0f && dxl * dxl >= thr) myl = true;
            jl -= 4;
            lmore = (jl >= 0) && (__ballot_sync(FULLMASK, !myl) != 0u);
        }
    }
#undef DIST
#undef INS

    // ---- local covariance of the 10 neighbors (centered on q) ----
    float mx = 0.f, my = 0.f, mz = 0.f;
#pragma unroll
    for (int r = 0; r < KNN; ++r) {
        float4 c = ss[a[r] & 0xFFFu];
        mx += c.x - q.x; my += c.y - q.y; mz += c.z - q.z;
    }
    const float invk = 1.0f / (float)KNN;
    mx *= invk; my *= invk; mz *= invk;

    float cxx = 0.f, cxy = 0.f, cxz = 0.f, cyy = 0.f, cyz = 0.f, czz = 0.f;
#pragma unroll
    for (int r = 0; r < KNN; ++r) {
        float4 c = ss[a[r] & 0xFFFu];
        float dx = (c.x - q.x) - mx;
        float dy = (c.y - q.y) - my;
        float dz = (c.z - q.z) - mz;
        cxx = fmaf(dx, dx, cxx); cxy = fmaf(dx, dy, cxy); cxz = fmaf(dx, dz, cxz);
        cyy = fmaf(dy, dy, cyy); cyz = fmaf(dy, dz, cyz); czz = fmaf(dz, dz, czz);
    }

    // ---- analytic smallest-eigenvector of 3x3 symmetric (double) ----
    double a00 = (double)cxx * invk, a01 = (double)cxy * invk, a02 = (double)cxz * invk;
    double a11 = (double)cyy * invk, a12 = (double)cyz * invk, a22 = (double)czz * invk;
    double vx = 1.0, vy = 0.0, vz = 0.0;

    double tr3 = (a00 + a11 + a22) * (1.0 / 3.0);
    double b00 = a00 - tr3, b11 = a11 - tr3, b22 = a22 - tr3;
    double p2 = b00 * b00 + b11 * b11 + b22 * b22
              + 2.0 * (a01 * a01 + a02 * a02 + a12 * a12);
    if (p2 > 0.0) {
        double pp = sqrt(p2 * (1.0 / 6.0));
        double ip = 1.0 / pp;
        double db00 = b00 * ip, db11 = b11 * ip, db22 = b22 * ip;
        double da01 = a01 * ip, da02 = a02 * ip, da12 = a12 * ip;
        double halfdet = 0.5 * (db00 * (db11 * db22 - da12 * da12)
                              - da01 * (da01 * db22 - da12 * da02)
                              + da02 * (da01 * da12 - db11 * da02));
        halfdet = fmin(fmax(halfdet, -1.0), 1.0);
        double ang  = acos(halfdet) * (1.0 / 3.0);
        double lmin = tr3 + 2.0 * pp * cos(ang + 2.0943951023931953);

        double m00 = a00 - lmin, m11 = a11 - lmin, m22 = a22 - lmin;
        double c1x = a01 * a12 - a02 * m11, c1y = a02 * a01 - m00 * a12, c1z = m00 * m11 - a01 * a01;
        double c2x = a01 * m22 - a02 * a12, c2y = a02 * a02 - m00 * m22, c2z = m00 * a12 - a01 * a02;
        double c3x = m11 * m22 - a12 * a12, c3y = a12 * a02 - a01 * m22, c3z = a01 * a12 - m11 * a02;
        double n1 = c1x * c1x + c1y * c1y + c1z * c1z;
        double n2 = c2x * c2x + c2y * c2y + c2z * c2z;
        double n3 = c3x * c3x + c3y * c3y + c3z * c3z;
        double bx = c1x, by = c1y, bz = c1z, bn = n1;
        if (n2 > bn) { bx = c2x; by = c2y; bz = c2z; bn = n2; }
        if (n3 > bn) { bx = c3x; by = c3y; bz = c3z; bn = n3; }
        if (bn > 1e-100) {
            double si = 1.0 / sqrt(bn);
            vx = bx * si; vy = by * si; vz = bz * si;
        } else {
            double r0n = m00 * m00 + a01 * a01 + a02 * a02;
            double r1n = a01 * a01 + m11 * m11 + a12 * a12;
            double r2n = a02 * a02 + a12 * a12 + m22 * m22;
            double wx = m00, wy = a01, wz = a02, wn = r0n;
            if (r1n > wn) { wx = a01; wy = m11; wz = a12; wn = r1n; }
            if (r2n > wn) { wx = a02; wy = a12; wz = m22; wn = r2n; }
            if (wn > 1e-100) {
                double fx = fabs(wx), fy = fabs(wy), fz = fabs(wz);
                double ex = 0.0, ey = 0.0, ez = 0.0;
                if (fx <= fy && fx <= fz) ex = 1.0;
                else if (fy <= fz)        ey = 1.0;
                else                      ez = 1.0;
                double ux = wy * ez - wz * ey;
                double uy = wz * ex - wx * ez;
                double uz = wx * ey - wy * ex;
                double un = ux * ux + uy * uy + uz * uz;
                double si = 1.0 / sqrt(un);
                vx = ux * si; vy = uy * si; vz = uz * si;
            }
        }
    }

    // scatter back to ORIGINAL point order so pred/gt pairing is preserved
    const int orig = (int)g_sidx[cloud][b][p];
    const int gi = b * NPTS + orig;
    g_nrm[cloud][0][gi] = (float)vx;
    g_nrm[cloud][1][gi] = (float)vy;
    g_nrm[cloud][2][gi] = (float)vz;
}

__global__ void loss_kernel(float* __restrict__ out) {
    __shared__ float wsum[TPB / 32];
    const int i = blockIdx.x * TPB + threadIdx.x;   // LOSS_BLOCKS*TPB == NB*NPTS
    float px = g_nrm[0][0][i], py = g_nrm[0][1][i], pz = g_nrm[0][2][i];
    float gx = g_nrm[1][0][i], gy = g_nrm[1][1][i], gz = g_nrm[1][2][i];
    float dot = px * gx + py * gy + pz * gz;
    float dn  = sqrtf(px * px + py * py + pz * pz)
              * sqrtf(gx * gx + gy * gy + gz * gz);
    float cs  = dot / fmaxf(dn, 1e-8f);
    float v   = 1.0f - fabsf(cs);
#pragma unroll
    for (int o = 16; o > 0; o >>= 1)
        v += __shfl_down_sync(FULLMASK, v, o);
    if ((threadIdx.x & 31) == 0) wsum[threadIdx.x >> 5] = v;
    __syncthreads();
    if (threadIdx.x < TPB / 32) {
        float b = wsum[threadIdx.x];
#pragma unroll
        for (int o = TPB / 64; o > 0; o >>= 1)
            b += __shfl_down_sync(0xFFu, b, o);
        if (threadIdx.x == 0)
            atomicAdd(out, b * (1.0f / (float)(NB * NPTS)));
    }
}

extern "C" void kernel_launch(void* const* d_in, const int* in_sizes, int n_in,
                              void* d_out, int out_size) {
    (void)in_sizes; (void)n_in; (void)out_size;
    const float* pred = (const float*)d_in[0];
    const float* gt   = (const float*)d_in[1];
    float* out = (float*)d_out;

    static bool attr_done = false;
    const int smem = NPTS * (int)sizeof(float4);   // 64 KB
    if (!attr_done) {
        cudaFuncSetAttribute(normals_kernel,
                             cudaFuncAttributeMaxDynamicSharedMemorySize, smem);
        attr_done = true;
    }

    sort_kernel<<<dim3(NB, 2), SORT_TPB>>>(pred, gt);
    dim3 grid(NPTS / TPB, NB, 2);
    normals_kernel<<<grid, TPB, smem>>>(out);
    loss_kernel<<<LOSS_BLOCKS, TPB>>>(out);
}